// round 14
// baseline (speedup 1.0000x reference)
#include <cuda_runtime.h>
#include <cuda_bf16.h>
#include <stdint.h>
#include <math.h>

// Problem constants
#define BB 8
#define LL 1024
#define SS 1000
#define DM 1024      // d_model = H*E
#define DL 4096      // d_llm
#define HH 16
#define EE 64

// ---------------- scratch (__device__ globals; no allocation allowed) -------
__device__ float g_Q[(size_t)BB * LL * DM];   // fp32 Q for attention
__device__ float g_K[(size_t)SS * DM];
__device__ float g_V[(size_t)SS * DM];

// split bf16 operands (hi + lo)
__device__ __nv_bfloat16 g_tgt_h[(size_t)BB * LL * DM];
__device__ __nv_bfloat16 g_tgt_l[(size_t)BB * LL * DM];
__device__ __nv_bfloat16 g_src_h[(size_t)SS * DL];
__device__ __nv_bfloat16 g_src_l[(size_t)SS * DL];
__device__ __nv_bfloat16 g_val_h[(size_t)SS * DL];
__device__ __nv_bfloat16 g_val_l[(size_t)SS * DL];
__device__ __nv_bfloat16 g_Wq_h[(size_t)DM * DM];
__device__ __nv_bfloat16 g_Wq_l[(size_t)DM * DM];
__device__ __nv_bfloat16 g_Wk_h[(size_t)DL * DM];
__device__ __nv_bfloat16 g_Wk_l[(size_t)DL * DM];
__device__ __nv_bfloat16 g_Wv_h[(size_t)DL * DM];
__device__ __nv_bfloat16 g_Wv_l[(size_t)DL * DM];
__device__ __nv_bfloat16 g_Wo_h[(size_t)DM * DL];
__device__ __nv_bfloat16 g_Wo_l[(size_t)DM * DL];
__device__ __nv_bfloat16 g_X_h[(size_t)BB * LL * DM];
__device__ __nv_bfloat16 g_X_l[(size_t)BB * LL * DM];

// ---------------------------------------------------------------------------
// fp32 -> (hi, lo) bf16 split, streaming. 8 floats per thread.
// ---------------------------------------------------------------------------
__global__ __launch_bounds__(256)
void split_kernel(const float4* __restrict__ in, uint4* __restrict__ hi,
                  uint4* __restrict__ lo, int n8)
{
    int i = blockIdx.x * 256 + threadIdx.x;
    if (i >= n8) return;
    float4 a = in[2 * i], b = in[2 * i + 1];
    float f[8] = {a.x, a.y, a.z, a.w, b.x, b.y, b.z, b.w};
    uint32_t hw[4], lw[4];
#pragma unroll
    for (int j = 0; j < 4; j++) {
        __nv_bfloat16 h0 = __float2bfloat16(f[2 * j]);
        __nv_bfloat16 h1 = __float2bfloat16(f[2 * j + 1]);
        __nv_bfloat16 l0 = __float2bfloat16(f[2 * j]     - __bfloat162float(h0));
        __nv_bfloat16 l1 = __float2bfloat16(f[2 * j + 1] - __bfloat162float(h1));
        __nv_bfloat162 H = __halves2bfloat162(h0, h1);
        __nv_bfloat162 L = __halves2bfloat162(l0, l1);
        hw[j] = *reinterpret_cast<uint32_t*>(&H);
        lw[j] = *reinterpret_cast<uint32_t*>(&L);
    }
    hi[i] = make_uint4(hw[0], hw[1], hw[2], hw[3]);
    lo[i] = make_uint4(lw[0], lw[1], lw[2], lw[3]);
}

// ---------------------------------------------------------------------------
// PTX helpers
// ---------------------------------------------------------------------------
__device__ __forceinline__ void cp16(uint32_t dst, const void* src, bool pred) {
    int sz = pred ? 16 : 0;
    asm volatile("cp.async.cg.shared.global [%0], [%1], 16, %2;\n"
                 :: "r"(dst), "l"(src), "r"(sz));
}
__device__ __forceinline__ void cp_commit() {
    asm volatile("cp.async.commit_group;\n");
}
template <int N> __device__ __forceinline__ void cp_wait() {
    asm volatile("cp.async.wait_group %0;\n" :: "n"(N));
}
__device__ __forceinline__ void ldsm4(uint32_t addr, uint32_t& r0, uint32_t& r1,
                                      uint32_t& r2, uint32_t& r3) {
    asm volatile("ldmatrix.sync.aligned.m8n8.x4.shared.b16 {%0,%1,%2,%3}, [%4];"
                 : "=r"(r0), "=r"(r1), "=r"(r2), "=r"(r3) : "r"(addr));
}
__device__ __forceinline__ void ldsm4t(uint32_t addr, uint32_t& r0, uint32_t& r1,
                                       uint32_t& r2, uint32_t& r3) {
    asm volatile("ldmatrix.sync.aligned.m8n8.x4.trans.shared.b16 {%0,%1,%2,%3}, [%4];"
                 : "=r"(r0), "=r"(r1), "=r"(r2), "=r"(r3) : "r"(addr));
}
__device__ __forceinline__ void mma16816(float* c, const uint32_t* a,
                                         uint32_t b0, uint32_t b1) {
    asm volatile(
        "mma.sync.aligned.m16n8k16.row.col.f32.bf16.bf16.f32 "
        "{%0,%1,%2,%3}, {%4,%5,%6,%7}, {%8,%9}, {%0,%1,%2,%3};"
        : "+f"(c[0]), "+f"(c[1]), "+f"(c[2]), "+f"(c[3])
        : "r"(a[0]), "r"(a[1]), "r"(a[2]), "r"(a[3]), "r"(b0), "r"(b1));
}

// ---------------------------------------------------------------------------
// Split-bf16 tensor-core GEMM on pre-split operands.
// C[M,N] = A @ B + bias;  A = Ah+Al ([M][K] bf16), B = Bh+Bl ([K][N] bf16).
// 128x128 tile, BK=32, 256 threads, cp.async double-buffered.
// A smem row-major (PADA), B smem k-major (PADB) + ldmatrix.trans.
// ---------------------------------------------------------------------------
#define PADA 40                 // 32 data + 8 pad bf16  (80 B rows)
#define PADB 136                // 128 data + 8 pad bf16 (272 B rows)
#define A_ST (128 * PADA)       // elems per A stage
#define B_ST (32 * PADB)        // elems per B stage
#define GSMEM ((4 * A_ST + 4 * B_ST) * 2)   // bytes = 75776

__global__ __launch_bounds__(256, 2)
void gemm_sp(const __nv_bfloat16* __restrict__ Ah, const __nv_bfloat16* __restrict__ Al,
             const __nv_bfloat16* __restrict__ Bh, const __nv_bfloat16* __restrict__ Bl,
             const float* __restrict__ bias, float* __restrict__ C,
             int M, int N, int K,
             const __nv_bfloat16* Ah2, const __nv_bfloat16* Al2,
             const __nv_bfloat16* Bh2, const __nv_bfloat16* Bl2,
             const float* bias2, float* C2)
{
    if (blockIdx.z) { Ah = Ah2; Al = Al2; Bh = Bh2; Bl = Bl2; bias = bias2; C = C2; }

    extern __shared__ __nv_bfloat16 sm[];
    __nv_bfloat16* sAh = sm;
    __nv_bfloat16* sAl = sm + 2 * A_ST;
    __nv_bfloat16* sBh = sm + 4 * A_ST;
    __nv_bfloat16* sBl = sm + 4 * A_ST + 2 * B_ST;

    const int tid  = threadIdx.x;
    const int lane = tid & 31;
    const int wid  = tid >> 5;
    const int wm   = wid >> 2;        // 0..1 : 64 rows
    const int wn   = wid & 3;         // 0..3 : 32 cols
    const int row0 = blockIdx.y * 128;
    const int col0 = blockIdx.x * 128;

    // ldmatrix lane addressing
    const int rF = lane & 15;                       // A: row within 16
    const int cF = (lane >> 4) << 3;                // A: k-half
    const int bR = ((lane >> 3) & 1) * 8 + (lane & 7);  // B: k-row within 16
    const int bC = (lane >> 4) << 3;                // B: n-half

    float acc[4][4][4];
#pragma unroll
    for (int a = 0; a < 4; a++)
#pragma unroll
        for (int b = 0; b < 4; b++)
#pragma unroll
            for (int c = 0; c < 4; c++) acc[a][b][c] = 0.f;

    const int KT = K >> 5;

    auto issue = [&](int kt) {
        const int k0 = kt << 5;
        const int st = kt & 1;
        __nv_bfloat16* dAh = sAh + st * A_ST;
        __nv_bfloat16* dAl = sAl + st * A_ST;
        __nv_bfloat16* dBh = sBh + st * B_ST;
        __nv_bfloat16* dBl = sBl + st * B_ST;
#pragma unroll
        for (int i = 0; i < 2; i++) {               // A: 128 rows x 64B
            int c   = tid + (i << 8);
            int row = c >> 2;
            int off = (c & 3) << 3;                 // elems
            bool p  = (row0 + row) < M;
            size_t go = (size_t)(row0 + (p ? row : 0)) * K + k0 + off;
            uint32_t d = (uint32_t)__cvta_generic_to_shared(dAh + row * PADA + off);
            cp16(d, Ah + go, p);
            d = (uint32_t)__cvta_generic_to_shared(dAl + row * PADA + off);
            cp16(d, Al + go, p);
        }
#pragma unroll
        for (int i = 0; i < 2; i++) {               // B: 32 rows x 256B
            int c   = tid + (i << 8);
            int row = c >> 4;
            int off = (c & 15) << 3;
            size_t go = (size_t)(k0 + row) * N + col0 + off;
            uint32_t d = (uint32_t)__cvta_generic_to_shared(dBh + row * PADB + off);
            cp16(d, Bh + go, true);
            d = (uint32_t)__cvta_generic_to_shared(dBl + row * PADB + off);
            cp16(d, Bl + go, true);
        }
        cp_commit();
    };

    auto compute = [&](int st) {
        const __nv_bfloat16* pAh = sAh + st * A_ST;
        const __nv_bfloat16* pAl = sAl + st * A_ST;
        const __nv_bfloat16* pBh = sBh + st * B_ST;
        const __nv_bfloat16* pBl = sBl + st * B_ST;
#pragma unroll
        for (int kk = 0; kk < 32; kk += 16) {
            uint32_t bh[2][4], bl[2][4];
#pragma unroll
            for (int p = 0; p < 2; p++) {
                int rr = kk + bR;
                int cc = wn * 32 + p * 16 + bC;
                ldsm4t((uint32_t)__cvta_generic_to_shared(pBh + rr * PADB + cc),
                       bh[p][0], bh[p][1], bh[p][2], bh[p][3]);
                ldsm4t((uint32_t)__cvta_generic_to_shared(pBl + rr * PADB + cc),
                       bl[p][0], bl[p][1], bl[p][2], bl[p][3]);
            }
#pragma unroll
            for (int mf = 0; mf < 4; mf++) {
                int r = wm * 64 + mf * 16 + rF;
                uint32_t ah[4], al[4];
                ldsm4((uint32_t)__cvta_generic_to_shared(pAh + r * PADA + kk + cF),
                      ah[0], ah[1], ah[2], ah[3]);
                ldsm4((uint32_t)__cvta_generic_to_shared(pAl + r * PADA + kk + cF),
                      al[0], al[1], al[2], al[3]);
#pragma unroll
                for (int p = 0; p < 2; p++) {
                    mma16816(acc[mf][2 * p],     ah, bh[p][0], bh[p][1]);
                    mma16816(acc[mf][2 * p],     al, bh[p][0], bh[p][1]);
                    mma16816(acc[mf][2 * p],     ah, bl[p][0], bl[p][1]);
                    mma16816(acc[mf][2 * p + 1], ah, bh[p][2], bh[p][3]);
                    mma16816(acc[mf][2 * p + 1], al, bh[p][2], bh[p][3]);
                    mma16816(acc[mf][2 * p + 1], ah, bl[p][2], bl[p][3]);
                }
            }
        }
    };

    issue(0);
    for (int kt = 0; kt < KT; kt++) {
        if (kt + 1 < KT) { issue(kt + 1); cp_wait<1>(); }
        else             { cp_wait<0>(); }
        __syncthreads();
        compute(kt & 1);
        __syncthreads();
    }

    // epilogue: bias + store
#pragma unroll
    for (int mf = 0; mf < 4; mf++) {
        int r = row0 + wm * 64 + mf * 16 + (lane >> 2);
#pragma unroll
        for (int half = 0; half < 2; half++) {
            int rr = r + half * 8;
            if (rr >= M) continue;
            float* crow = C + (size_t)rr * N;
#pragma unroll
            for (int nf = 0; nf < 4; nf++) {
                int cc = col0 + wn * 32 + nf * 8 + (lane & 3) * 2;
                float2 bv = *(const float2*)(bias + cc);
                float2 o;
                o.x = acc[mf][nf][half * 2 + 0] + bv.x;
                o.y = acc[mf][nf][half * 2 + 1] + bv.y;
                *(float2*)(crow + cc) = o;
            }
        }
    }
}

// ---------------------------------------------------------------------------
// Fused attention; writes X directly as split bf16 for the Wo GEMM.
// ---------------------------------------------------------------------------
#define ATS 64

__global__ __launch_bounds__(128)
void attn_kernel(const float* __restrict__ Q, const float* __restrict__ K,
                 const float* __restrict__ V,
                 __nv_bfloat16* __restrict__ Xh, __nv_bfloat16* __restrict__ Xl)
{
    __shared__ float Ks[ATS][EE];
    __shared__ float Vs[ATS][EE];

    const int tid = threadIdx.x;
    const int bh  = blockIdx.y;
    const int b   = bh >> 4;
    const int h   = bh & 15;
    const int l   = blockIdx.x * 128 + tid;
    const size_t r = (size_t)b * LL + l;

    float q[EE];
    {
        const float4* qp = (const float4*)(Q + r * DM + h * EE);
#pragma unroll
        for (int i = 0; i < EE / 4; i++) {
            float4 t = qp[i];
            q[4 * i + 0] = t.x; q[4 * i + 1] = t.y;
            q[4 * i + 2] = t.z; q[4 * i + 3] = t.w;
        }
    }

    float o[EE];
#pragma unroll
    for (int e = 0; e < EE; e++) o[e] = 0.f;
    float mx = -1e30f, ssum = 0.f;
    const float scale = 0.125f;

    for (int s0 = 0; s0 < SS; s0 += ATS) {
        const int cnt = min(ATS, SS - s0);
        __syncthreads();
        for (int i = tid; i < ATS * (EE / 4); i += 128) {
            int row = i >> 4;
            int c4  = (i & 15) * 4;
            float4 kv = make_float4(0.f, 0.f, 0.f, 0.f);
            float4 vv = make_float4(0.f, 0.f, 0.f, 0.f);
            if (row < cnt) {
                size_t base = (size_t)(s0 + row) * DM + h * EE + c4;
                kv = *(const float4*)(K + base);
                vv = *(const float4*)(V + base);
            }
            *(float4*)&Ks[row][c4] = kv;
            *(float4*)&Vs[row][c4] = vv;
        }
        __syncthreads();

        for (int j = 0; j < cnt; j++) {
            float s = 0.f;
            const float4* kr = (const float4*)Ks[j];
#pragma unroll
            for (int i = 0; i < EE / 4; i++) {
                float4 t = kr[i];
                s += q[4 * i + 0] * t.x + q[4 * i + 1] * t.y
                   + q[4 * i + 2] * t.z + q[4 * i + 3] * t.w;
            }
            s *= scale;
            if (s > mx) {
                float c = __expf(mx - s);
                ssum *= c;
#pragma unroll
                for (int e = 0; e < EE; e++) o[e] *= c;
                mx = s;
            }
            float p = __expf(s - mx);
            ssum += p;
            const float4* vr = (const float4*)Vs[j];
#pragma unroll
            for (int i = 0; i < EE / 4; i++) {
                float4 t = vr[i];
                o[4 * i + 0] += p * t.x; o[4 * i + 1] += p * t.y;
                o[4 * i + 2] += p * t.z; o[4 * i + 3] += p * t.w;
            }
        }
    }

    const float inv = 1.f / ssum;
    const size_t base = r * DM + h * EE;
#pragma unroll
    for (int i = 0; i < EE / 2; i++) {
        float v0 = o[2 * i] * inv, v1 = o[2 * i + 1] * inv;
        __nv_bfloat16 h0 = __float2bfloat16(v0);
        __nv_bfloat16 h1 = __float2bfloat16(v1);
        __nv_bfloat16 l0 = __float2bfloat16(v0 - __bfloat162float(h0));
        __nv_bfloat16 l1 = __float2bfloat16(v1 - __bfloat162float(h1));
        *(__nv_bfloat162*)(Xh + base + 2 * i) = __halves2bfloat162(h0, h1);
        *(__nv_bfloat162*)(Xl + base + 2 * i) = __halves2bfloat162(l0, l1);
    }
}

// ---------------------------------------------------------------------------
extern "C" void kernel_launch(void* const* d_in, const int* in_sizes, int n_in,
                              void* d_out, int out_size)
{
    const float* tgt = (const float*)d_in[0];
    const float* src = (const float*)d_in[1];
    const float* val = (const float*)d_in[2];
    const float* Wq  = (const float*)d_in[3];
    const float* bq  = (const float*)d_in[4];
    const float* Wk  = (const float*)d_in[5];
    const float* bk  = (const float*)d_in[6];
    const float* Wv  = (const float*)d_in[7];
    const float* bv  = (const float*)d_in[8];
    const float* Wo  = (const float*)d_in[9];
    const float* bo  = (const float*)d_in[10];
    float* out = (float*)d_out;

    float *Qb, *Kb, *Vb;
    cudaGetSymbolAddress((void**)&Qb, g_Q);
    cudaGetSymbolAddress((void**)&Kb, g_K);
    cudaGetSymbolAddress((void**)&Vb, g_V);

    __nv_bfloat16 *tgtH, *tgtL, *srcH, *srcL, *valH, *valL;
    __nv_bfloat16 *WqH, *WqL, *WkH, *WkL, *WvH, *WvL, *WoH, *WoL, *XH, *XL;
    cudaGetSymbolAddress((void**)&tgtH, g_tgt_h); cudaGetSymbolAddress((void**)&tgtL, g_tgt_l);
    cudaGetSymbolAddress((void**)&srcH, g_src_h); cudaGetSymbolAddress((void**)&srcL, g_src_l);
    cudaGetSymbolAddress((void**)&valH, g_val_h); cudaGetSymbolAddress((void**)&valL, g_val_l);
    cudaGetSymbolAddress((void**)&WqH, g_Wq_h);   cudaGetSymbolAddress((void**)&WqL, g_Wq_l);
    cudaGetSymbolAddress((void**)&WkH, g_Wk_h);   cudaGetSymbolAddress((void**)&WkL, g_Wk_l);
    cudaGetSymbolAddress((void**)&WvH, g_Wv_h);   cudaGetSymbolAddress((void**)&WvL, g_Wv_l);
    cudaGetSymbolAddress((void**)&WoH, g_Wo_h);   cudaGetSymbolAddress((void**)&WoL, g_Wo_l);
    cudaGetSymbolAddress((void**)&XH,  g_X_h);    cudaGetSymbolAddress((void**)&XL,  g_X_l);

    cudaFuncSetAttribute(gemm_sp, cudaFuncAttributeMaxDynamicSharedMemorySize, GSMEM);

    // ---- split pre-passes ----
    auto split = [](const float* p, __nv_bfloat16* h, __nv_bfloat16* l, size_t n) {
        int n8 = (int)(n / 8);
        split_kernel<<<(n8 + 255) / 256, 256>>>((const float4*)p, (uint4*)h, (uint4*)l, n8);
    };
    split(tgt, tgtH, tgtL, (size_t)BB * LL * DM);
    split(src, srcH, srcL, (size_t)SS * DL);
    split(val, valH, valL, (size_t)SS * DL);
    split(Wq,  WqH,  WqL,  (size_t)DM * DM);
    split(Wk,  WkH,  WkL,  (size_t)DL * DM);
    split(Wv,  WvH,  WvL,  (size_t)DL * DM);
    split(Wo,  WoH,  WoL,  (size_t)DM * DL);

    // ---- Q = tgt @ Wq + bq    M=8192, N=1024, K=1024 ----
    gemm_sp<<<dim3(DM / 128, (BB * LL) / 128, 1), 256, GSMEM>>>(
        tgtH, tgtL, WqH, WqL, bq, Qb, BB * LL, DM, DM,
        nullptr, nullptr, nullptr, nullptr, nullptr, nullptr);

    // ---- K/V projections fused (z=2)   M=1000, N=1024, K=4096 ----
    gemm_sp<<<dim3(DM / 128, (SS + 127) / 128, 2), 256, GSMEM>>>(
        srcH, srcL, WkH, WkL, bk, Kb, SS, DM, DL,
        valH, valL, WvH, WvL, bv, Vb);

    // ---- attention (writes split X) ----
    attn_kernel<<<dim3(LL / 128, BB * HH), 128>>>(Qb, Kb, Vb, XH, XL);

    // ---- out = X @ Wo + bo    M=8192, N=4096, K=1024 ----
    gemm_sp<<<dim3(DL / 128, (BB * LL) / 128, 1), 256, GSMEM>>>(
        XH, XL, WoH, WoL, bo, out, BB * LL, DL, DM,
        nullptr, nullptr, nullptr, nullptr, nullptr, nullptr);
}

// round 15
// speedup vs baseline: 1.0004x; 1.0004x over previous
#include <cuda_runtime.h>
#include <cuda_bf16.h>
#include <stdint.h>
#include <math.h>

// Problem constants
#define BB 8
#define LL 1024
#define SS 1000
#define DM 1024      // d_model = H*E
#define DL 4096      // d_llm
#define HH 16
#define EE 64

// ---------------- scratch (__device__ globals; no allocation allowed) -------
__device__ float g_Q[(size_t)BB * LL * DM];   // fp32 Q for attention
__device__ float g_K[(size_t)SS * DM];
__device__ float g_V[(size_t)SS * DM];

// split bf16 operands (hi + lo)
__device__ __nv_bfloat16 g_tgt_h[(size_t)BB * LL * DM];
__device__ __nv_bfloat16 g_tgt_l[(size_t)BB * LL * DM];
__device__ __nv_bfloat16 g_src_h[(size_t)SS * DL];
__device__ __nv_bfloat16 g_src_l[(size_t)SS * DL];
__device__ __nv_bfloat16 g_val_h[(size_t)SS * DL];
__device__ __nv_bfloat16 g_val_l[(size_t)SS * DL];
__device__ __nv_bfloat16 g_Wq_h[(size_t)DM * DM];
__device__ __nv_bfloat16 g_Wq_l[(size_t)DM * DM];
__device__ __nv_bfloat16 g_Wk_h[(size_t)DL * DM];
__device__ __nv_bfloat16 g_Wk_l[(size_t)DL * DM];
__device__ __nv_bfloat16 g_Wv_h[(size_t)DL * DM];
__device__ __nv_bfloat16 g_Wv_l[(size_t)DL * DM];
__device__ __nv_bfloat16 g_Wo_h[(size_t)DM * DL];
__device__ __nv_bfloat16 g_Wo_l[(size_t)DM * DL];
__device__ __nv_bfloat16 g_X_h[(size_t)BB * LL * DM];
__device__ __nv_bfloat16 g_X_l[(size_t)BB * LL * DM];

// ---------------------------------------------------------------------------
// fp32 -> (hi, lo) bf16 split, streaming. 8 floats per thread.
// ---------------------------------------------------------------------------
__global__ __launch_bounds__(256)
void split_kernel(const float4* __restrict__ in, uint4* __restrict__ hi,
                  uint4* __restrict__ lo, int n8)
{
    int i = blockIdx.x * 256 + threadIdx.x;
    if (i >= n8) return;
    float4 a = in[2 * i], b = in[2 * i + 1];
    float f[8] = {a.x, a.y, a.z, a.w, b.x, b.y, b.z, b.w};
    uint32_t hw[4], lw[4];
#pragma unroll
    for (int j = 0; j < 4; j++) {
        __nv_bfloat16 h0 = __float2bfloat16(f[2 * j]);
        __nv_bfloat16 h1 = __float2bfloat16(f[2 * j + 1]);
        __nv_bfloat16 l0 = __float2bfloat16(f[2 * j]     - __bfloat162float(h0));
        __nv_bfloat16 l1 = __float2bfloat16(f[2 * j + 1] - __bfloat162float(h1));
        __nv_bfloat162 H = __halves2bfloat162(h0, h1);
        __nv_bfloat162 L = __halves2bfloat162(l0, l1);
        hw[j] = *reinterpret_cast<uint32_t*>(&H);
        lw[j] = *reinterpret_cast<uint32_t*>(&L);
    }
    hi[i] = make_uint4(hw[0], hw[1], hw[2], hw[3]);
    lo[i] = make_uint4(lw[0], lw[1], lw[2], lw[3]);
}

// ---------------------------------------------------------------------------
// PTX helpers
// ---------------------------------------------------------------------------
__device__ __forceinline__ void cp16(uint32_t dst, const void* src, bool pred) {
    int sz = pred ? 16 : 0;
    asm volatile("cp.async.cg.shared.global [%0], [%1], 16, %2;\n"
                 :: "r"(dst), "l"(src), "r"(sz));
}
__device__ __forceinline__ void cp_commit() {
    asm volatile("cp.async.commit_group;\n");
}
template <int N> __device__ __forceinline__ void cp_wait() {
    asm volatile("cp.async.wait_group %0;\n" :: "n"(N));
}
__device__ __forceinline__ void ldsm4(uint32_t addr, uint32_t& r0, uint32_t& r1,
                                      uint32_t& r2, uint32_t& r3) {
    asm volatile("ldmatrix.sync.aligned.m8n8.x4.shared.b16 {%0,%1,%2,%3}, [%4];"
                 : "=r"(r0), "=r"(r1), "=r"(r2), "=r"(r3) : "r"(addr));
}
__device__ __forceinline__ void ldsm4t(uint32_t addr, uint32_t& r0, uint32_t& r1,
                                       uint32_t& r2, uint32_t& r3) {
    asm volatile("ldmatrix.sync.aligned.m8n8.x4.trans.shared.b16 {%0,%1,%2,%3}, [%4];"
                 : "=r"(r0), "=r"(r1), "=r"(r2), "=r"(r3) : "r"(addr));
}
__device__ __forceinline__ void mma16816(float* c, const uint32_t* a,
                                         uint32_t b0, uint32_t b1) {
    asm volatile(
        "mma.sync.aligned.m16n8k16.row.col.f32.bf16.bf16.f32 "
        "{%0,%1,%2,%3}, {%4,%5,%6,%7}, {%8,%9}, {%0,%1,%2,%3};"
        : "+f"(c[0]), "+f"(c[1]), "+f"(c[2]), "+f"(c[3])
        : "r"(a[0]), "r"(a[1]), "r"(a[2]), "r"(a[3]), "r"(b0), "r"(b1));
}

// ---------------------------------------------------------------------------
// Split-bf16 tensor-core GEMM on pre-split operands.
// C[M,N] = A @ B + bias;  A = Ah+Al ([M][K] bf16), B = Bh+Bl ([K][N] bf16).
// 128x128 tile, BK=32, 256 threads, cp.async double-buffered.
// A smem row-major (PADA), B smem k-major (PADB) + ldmatrix.trans.
// ---------------------------------------------------------------------------
#define PADA 40                 // 32 data + 8 pad bf16  (80 B rows)
#define PADB 136                // 128 data + 8 pad bf16 (272 B rows)
#define A_ST (128 * PADA)       // elems per A stage
#define B_ST (32 * PADB)        // elems per B stage
#define GSMEM ((4 * A_ST + 4 * B_ST) * 2)   // bytes = 75776

__global__ __launch_bounds__(256, 2)
void gemm_sp(const __nv_bfloat16* __restrict__ Ah, const __nv_bfloat16* __restrict__ Al,
             const __nv_bfloat16* __restrict__ Bh, const __nv_bfloat16* __restrict__ Bl,
             const float* __restrict__ bias, float* __restrict__ C,
             int M, int N, int K,
             const __nv_bfloat16* Ah2, const __nv_bfloat16* Al2,
             const __nv_bfloat16* Bh2, const __nv_bfloat16* Bl2,
             const float* bias2, float* C2)
{
    if (blockIdx.z) { Ah = Ah2; Al = Al2; Bh = Bh2; Bl = Bl2; bias = bias2; C = C2; }

    extern __shared__ __nv_bfloat16 sm[];
    __nv_bfloat16* sAh = sm;
    __nv_bfloat16* sAl = sm + 2 * A_ST;
    __nv_bfloat16* sBh = sm + 4 * A_ST;
    __nv_bfloat16* sBl = sm + 4 * A_ST + 2 * B_ST;

    const int tid  = threadIdx.x;
    const int lane = tid & 31;
    const int wid  = tid >> 5;
    const int wm   = wid >> 2;        // 0..1 : 64 rows
    const int wn   = wid & 3;         // 0..3 : 32 cols
    const int row0 = blockIdx.y * 128;
    const int col0 = blockIdx.x * 128;

    // ldmatrix lane addressing
    const int rF = lane & 15;                       // A: row within 16
    const int cF = (lane >> 4) << 3;                // A: k-half
    const int bR = ((lane >> 3) & 1) * 8 + (lane & 7);  // B: k-row within 16
    const int bC = (lane >> 4) << 3;                // B: n-half

    float acc[4][4][4];
#pragma unroll
    for (int a = 0; a < 4; a++)
#pragma unroll
        for (int b = 0; b < 4; b++)
#pragma unroll
            for (int c = 0; c < 4; c++) acc[a][b][c] = 0.f;

    const int KT = K >> 5;

    auto issue = [&](int kt) {
        const int k0 = kt << 5;
        const int st = kt & 1;
        __nv_bfloat16* dAh = sAh + st * A_ST;
        __nv_bfloat16* dAl = sAl + st * A_ST;
        __nv_bfloat16* dBh = sBh + st * B_ST;
        __nv_bfloat16* dBl = sBl + st * B_ST;
#pragma unroll
        for (int i = 0; i < 2; i++) {               // A: 128 rows x 64B
            int c   = tid + (i << 8);
            int row = c >> 2;
            int off = (c & 3) << 3;                 // elems
            bool p  = (row0 + row) < M;
            size_t go = (size_t)(row0 + (p ? row : 0)) * K + k0 + off;
            uint32_t d = (uint32_t)__cvta_generic_to_shared(dAh + row * PADA + off);
            cp16(d, Ah + go, p);
            d = (uint32_t)__cvta_generic_to_shared(dAl + row * PADA + off);
            cp16(d, Al + go, p);
        }
#pragma unroll
        for (int i = 0; i < 2; i++) {               // B: 32 rows x 256B
            int c   = tid + (i << 8);
            int row = c >> 4;
            int off = (c & 15) << 3;
            size_t go = (size_t)(k0 + row) * N + col0 + off;
            uint32_t d = (uint32_t)__cvta_generic_to_shared(dBh + row * PADB + off);
            cp16(d, Bh + go, true);
            d = (uint32_t)__cvta_generic_to_shared(dBl + row * PADB + off);
            cp16(d, Bl + go, true);
        }
        cp_commit();
    };

    auto compute = [&](int st) {
        const __nv_bfloat16* pAh = sAh + st * A_ST;
        const __nv_bfloat16* pAl = sAl + st * A_ST;
        const __nv_bfloat16* pBh = sBh + st * B_ST;
        const __nv_bfloat16* pBl = sBl + st * B_ST;
#pragma unroll
        for (int kk = 0; kk < 32; kk += 16) {
            uint32_t bh[2][4], bl[2][4];
#pragma unroll
            for (int p = 0; p < 2; p++) {
                int rr = kk + bR;
                int cc = wn * 32 + p * 16 + bC;
                ldsm4t((uint32_t)__cvta_generic_to_shared(pBh + rr * PADB + cc),
                       bh[p][0], bh[p][1], bh[p][2], bh[p][3]);
                ldsm4t((uint32_t)__cvta_generic_to_shared(pBl + rr * PADB + cc),
                       bl[p][0], bl[p][1], bl[p][2], bl[p][3]);
            }
#pragma unroll
            for (int mf = 0; mf < 4; mf++) {
                int r = wm * 64 + mf * 16 + rF;
                uint32_t ah[4], al[4];
                ldsm4((uint32_t)__cvta_generic_to_shared(pAh + r * PADA + kk + cF),
                      ah[0], ah[1], ah[2], ah[3]);
                ldsm4((uint32_t)__cvta_generic_to_shared(pAl + r * PADA + kk + cF),
                      al[0], al[1], al[2], al[3]);
#pragma unroll
                for (int p = 0; p < 2; p++) {
                    mma16816(acc[mf][2 * p],     ah, bh[p][0], bh[p][1]);
                    mma16816(acc[mf][2 * p],     al, bh[p][0], bh[p][1]);
                    mma16816(acc[mf][2 * p],     ah, bl[p][0], bl[p][1]);
                    mma16816(acc[mf][2 * p + 1], ah, bh[p][2], bh[p][3]);
                    mma16816(acc[mf][2 * p + 1], al, bh[p][2], bh[p][3]);
                    mma16816(acc[mf][2 * p + 1], ah, bl[p][2], bl[p][3]);
                }
            }
        }
    };

    issue(0);
    for (int kt = 0; kt < KT; kt++) {
        if (kt + 1 < KT) { issue(kt + 1); cp_wait<1>(); }
        else             { cp_wait<0>(); }
        __syncthreads();
        compute(kt & 1);
        __syncthreads();
    }

    // epilogue: bias + store
#pragma unroll
    for (int mf = 0; mf < 4; mf++) {
        int r = row0 + wm * 64 + mf * 16 + (lane >> 2);
#pragma unroll
        for (int half = 0; half < 2; half++) {
            int rr = r + half * 8;
            if (rr >= M) continue;
            float* crow = C + (size_t)rr * N;
#pragma unroll
            for (int nf = 0; nf < 4; nf++) {
                int cc = col0 + wn * 32 + nf * 8 + (lane & 3) * 2;
                float2 bv = *(const float2*)(bias + cc);
                float2 o;
                o.x = acc[mf][nf][half * 2 + 0] + bv.x;
                o.y = acc[mf][nf][half * 2 + 1] + bv.y;
                *(float2*)(crow + cc) = o;
            }
        }
    }
}

// ---------------------------------------------------------------------------
// Fused attention; writes X directly as split bf16 for the Wo GEMM.
// ---------------------------------------------------------------------------
#define ATS 64

__global__ __launch_bounds__(128)
void attn_kernel(const float* __restrict__ Q, const float* __restrict__ K,
                 const float* __restrict__ V,
                 __nv_bfloat16* __restrict__ Xh, __nv_bfloat16* __restrict__ Xl)
{
    __shared__ float Ks[ATS][EE];
    __shared__ float Vs[ATS][EE];

    const int tid = threadIdx.x;
    const int bh  = blockIdx.y;
    const int b   = bh >> 4;
    const int h   = bh & 15;
    const int l   = blockIdx.x * 128 + tid;
    const size_t r = (size_t)b * LL + l;

    float q[EE];
    {
        const float4* qp = (const float4*)(Q + r * DM + h * EE);
#pragma unroll
        for (int i = 0; i < EE / 4; i++) {
            float4 t = qp[i];
            q[4 * i + 0] = t.x; q[4 * i + 1] = t.y;
            q[4 * i + 2] = t.z; q[4 * i + 3] = t.w;
        }
    }

    float o[EE];
#pragma unroll
    for (int e = 0; e < EE; e++) o[e] = 0.f;
    float mx = -1e30f, ssum = 0.f;
    const float scale = 0.125f;

    for (int s0 = 0; s0 < SS; s0 += ATS) {
        const int cnt = min(ATS, SS - s0);
        __syncthreads();
        for (int i = tid; i < ATS * (EE / 4); i += 128) {
            int row = i >> 4;
            int c4  = (i & 15) * 4;
            float4 kv = make_float4(0.f, 0.f, 0.f, 0.f);
            float4 vv = make_float4(0.f, 0.f, 0.f, 0.f);
            if (row < cnt) {
                size_t base = (size_t)(s0 + row) * DM + h * EE + c4;
                kv = *(const float4*)(K + base);
                vv = *(const float4*)(V + base);
            }
            *(float4*)&Ks[row][c4] = kv;
            *(float4*)&Vs[row][c4] = vv;
        }
        __syncthreads();

        for (int j = 0; j < cnt; j++) {
            float s = 0.f;
            const float4* kr = (const float4*)Ks[j];
#pragma unroll
            for (int i = 0; i < EE / 4; i++) {
                float4 t = kr[i];
                s += q[4 * i + 0] * t.x + q[4 * i + 1] * t.y
                   + q[4 * i + 2] * t.z + q[4 * i + 3] * t.w;
            }
            s *= scale;
            if (s > mx) {
                float c = __expf(mx - s);
                ssum *= c;
#pragma unroll
                for (int e = 0; e < EE; e++) o[e] *= c;
                mx = s;
            }
            float p = __expf(s - mx);
            ssum += p;
            const float4* vr = (const float4*)Vs[j];
#pragma unroll
            for (int i = 0; i < EE / 4; i++) {
                float4 t = vr[i];
                o[4 * i + 0] += p * t.x; o[4 * i + 1] += p * t.y;
                o[4 * i + 2] += p * t.z; o[4 * i + 3] += p * t.w;
            }
        }
    }

    const float inv = 1.f / ssum;
    const size_t base = r * DM + h * EE;
#pragma unroll
    for (int i = 0; i < EE / 2; i++) {
        float v0 = o[2 * i] * inv, v1 = o[2 * i + 1] * inv;
        __nv_bfloat16 h0 = __float2bfloat16(v0);
        __nv_bfloat16 h1 = __float2bfloat16(v1);
        __nv_bfloat16 l0 = __float2bfloat16(v0 - __bfloat162float(h0));
        __nv_bfloat16 l1 = __float2bfloat16(v1 - __bfloat162float(h1));
        *(__nv_bfloat162*)(Xh + base + 2 * i) = __halves2bfloat162(h0, h1);
        *(__nv_bfloat162*)(Xl + base + 2 * i) = __halves2bfloat162(l0, l1);
    }
}

// ---------------------------------------------------------------------------
extern "C" void kernel_launch(void* const* d_in, const int* in_sizes, int n_in,
                              void* d_out, int out_size)
{
    const float* tgt = (const float*)d_in[0];
    const float* src = (const float*)d_in[1];
    const float* val = (const float*)d_in[2];
    const float* Wq  = (const float*)d_in[3];
    const float* bq  = (const float*)d_in[4];
    const float* Wk  = (const float*)d_in[5];
    const float* bk  = (const float*)d_in[6];
    const float* Wv  = (const float*)d_in[7];
    const float* bv  = (const float*)d_in[8];
    const float* Wo  = (const float*)d_in[9];
    const float* bo  = (const float*)d_in[10];
    float* out = (float*)d_out;

    float *Qb, *Kb, *Vb;
    cudaGetSymbolAddress((void**)&Qb, g_Q);
    cudaGetSymbolAddress((void**)&Kb, g_K);
    cudaGetSymbolAddress((void**)&Vb, g_V);

    __nv_bfloat16 *tgtH, *tgtL, *srcH, *srcL, *valH, *valL;
    __nv_bfloat16 *WqH, *WqL, *WkH, *WkL, *WvH, *WvL, *WoH, *WoL, *XH, *XL;
    cudaGetSymbolAddress((void**)&tgtH, g_tgt_h); cudaGetSymbolAddress((void**)&tgtL, g_tgt_l);
    cudaGetSymbolAddress((void**)&srcH, g_src_h); cudaGetSymbolAddress((void**)&srcL, g_src_l);
    cudaGetSymbolAddress((void**)&valH, g_val_h); cudaGetSymbolAddress((void**)&valL, g_val_l);
    cudaGetSymbolAddress((void**)&WqH, g_Wq_h);   cudaGetSymbolAddress((void**)&WqL, g_Wq_l);
    cudaGetSymbolAddress((void**)&WkH, g_Wk_h);   cudaGetSymbolAddress((void**)&WkL, g_Wk_l);
    cudaGetSymbolAddress((void**)&WvH, g_Wv_h);   cudaGetSymbolAddress((void**)&WvL, g_Wv_l);
    cudaGetSymbolAddress((void**)&WoH, g_Wo_h);   cudaGetSymbolAddress((void**)&WoL, g_Wo_l);
    cudaGetSymbolAddress((void**)&XH,  g_X_h);    cudaGetSymbolAddress((void**)&XL,  g_X_l);

    cudaFuncSetAttribute(gemm_sp, cudaFuncAttributeMaxDynamicSharedMemorySize, GSMEM);

    // ---- split pre-passes ----
    auto split = [](const float* p, __nv_bfloat16* h, __nv_bfloat16* l, size_t n) {
        int n8 = (int)(n / 8);
        split_kernel<<<(n8 + 255) / 256, 256>>>((const float4*)p, (uint4*)h, (uint4*)l, n8);
    };
    split(tgt, tgtH, tgtL, (size_t)BB * LL * DM);
    split(src, srcH, srcL, (size_t)SS * DL);
    split(val, valH, valL, (size_t)SS * DL);
    split(Wq,  WqH,  WqL,  (size_t)DM * DM);
    split(Wk,  WkH,  WkL,  (size_t)DL * DM);
    split(Wv,  WvH,  WvL,  (size_t)DL * DM);
    split(Wo,  WoH,  WoL,  (size_t)DM * DL);

    // ---- Q = tgt @ Wq + bq    M=8192, N=1024, K=1024 ----
    gemm_sp<<<dim3(DM / 128, (BB * LL) / 128, 1), 256, GSMEM>>>(
        tgtH, tgtL, WqH, WqL, bq, Qb, BB * LL, DM, DM,
        nullptr, nullptr, nullptr, nullptr, nullptr, nullptr);

    // ---- K/V projections fused (z=2)   M=1000, N=1024, K=4096 ----
    gemm_sp<<<dim3(DM / 128, (SS + 127) / 128, 2), 256, GSMEM>>>(
        srcH, srcL, WkH, WkL, bk, Kb, SS, DM, DL,
        valH, valL, WvH, WvL, bv, Vb);

    // ---- attention (writes split X) ----
    attn_kernel<<<dim3(LL / 128, BB * HH), 128>>>(Qb, Kb, Vb, XH, XL);

    // ---- out = X @ Wo + bo    M=8192, N=4096, K=1024 ----
    gemm_sp<<<dim3(DL / 128, (BB * LL) / 128, 1), 256, GSMEM>>>(
        XH, XL, WoH, WoL, bo, out, BB * LL, DL, DM,
        nullptr, nullptr, nullptr, nullptr, nullptr, nullptr);
}